// round 3
// baseline (speedup 1.0000x reference)
#include <cuda_runtime.h>
#include <cstdint>
#include <cstddef>

namespace {

constexpr int BM = 128;        // batch rows per CTA
constexpr int BN = 64;         // hidden cols per CTA (per gate; x4 gates)
constexpr int KB = 32;         // K elements per pipeline chunk
constexpr int STAGES = 3;
constexpr int KITERS = 2048 / KB;  // 64
constexpr int HDIM = 1024;
constexpr int BATCHSZ = 16384;

constexpr uint32_t A_BYTES = (uint32_t)BM * 128;        // 128 rows x 128B = 16 KB
constexpr uint32_t B_BYTES = (uint32_t)(4 * BN) * 128;  // 256 rows x 128B = 32 KB
constexpr uint32_t STAGE_BYTES = A_BYTES + B_BYTES;     // 48 KB
constexpr uint32_t SMEM_TOTAL = STAGES * STAGE_BYTES;   // 144 KB

__device__ __forceinline__ uint32_t smem_u32(const void* p) {
    uint32_t a;
    asm("{ .reg .u64 t; cvta.to.shared.u64 t, %1; cvt.u32.u64 %0, t; }" : "=r"(a) : "l"(p));
    return a;
}

__device__ __forceinline__ void cp16(uint32_t dst, const void* src) {
    asm volatile("cp.async.cg.shared.global [%0], [%1], 16;" :: "r"(dst), "l"(src));
}
__device__ __forceinline__ void cp_commit() { asm volatile("cp.async.commit_group;" ::: "memory"); }
__device__ __forceinline__ void cp_wait2()  { asm volatile("cp.async.wait_group 2;" ::: "memory"); }

// fp32 -> tf32 with round-to-nearest (unbiased; truncation would cost ~2x error)
__device__ __forceinline__ uint32_t f2tf(float x) {
    uint32_t r; asm("cvt.rna.tf32.f32 %0, %1;" : "=r"(r) : "f"(x)); return r;
}

__device__ __forceinline__ void mma_tf32(float (&d)[4], const uint32_t (&a)[4],
                                         uint32_t b0, uint32_t b1) {
    asm volatile(
        "mma.sync.aligned.m16n8k8.row.col.f32.tf32.tf32.f32 "
        "{%0,%1,%2,%3}, {%4,%5,%6,%7}, {%8,%9}, {%0,%1,%2,%3};"
        : "+f"(d[0]), "+f"(d[1]), "+f"(d[2]), "+f"(d[3])
        : "r"(a[0]), "r"(a[1]), "r"(a[2]), "r"(a[3]), "r"(b0), "r"(b1));
}

// swizzled scalar element address within a 128B-row tile region
__device__ __forceinline__ float lds_elem(const char* region, int row, int k) {
    return *(const float*)(region + row * 128 + (((uint32_t)k << 2) ^ (((uint32_t)(row & 7)) << 4)));
}

__device__ __forceinline__ float sig_e(float x) {
    return __fdividef(1.0f, 1.0f + __expf(-x));
}
__device__ __forceinline__ float tanh_e(float x) {
    return __fdividef(2.0f, 1.0f + __expf(-2.0f * x)) - 1.0f;
}

__global__ void __launch_bounds__(256, 1)
lstm_kernel(const float* __restrict__ X, const float* __restrict__ Cprev,
            const float* __restrict__ Hprev,
            const float* __restrict__ Wf, const float* __restrict__ Bf,
            const float* __restrict__ Wi, const float* __restrict__ Bi,
            const float* __restrict__ Wc, const float* __restrict__ Bc,
            const float* __restrict__ Wo, const float* __restrict__ Bo,
            float* __restrict__ Out)
{
    extern __shared__ char smem[];
    const uint32_t sb = smem_u32(smem);
    const int tid  = threadIdx.x;
    const int wid  = tid >> 5;
    const int lane = tid & 31;
    const int wm   = wid & 3;     // M block of warp (32 rows)
    const int wn   = wid >> 2;    // N block of warp (32 cols of the 64-col gate tile)
    const int n0 = blockIdx.x * BN;    // hidden col base
    const int m0 = blockIdx.y * BM;    // batch row base

    // ---- async loader for one stage: A tile + 4 gate B tiles, K-chunk ki ----
    auto load_stage = [&](int s, int ki) {
        const uint32_t base = sb + (uint32_t)s * STAGE_BYTES;
        // A: 128 rows x 128B, 2 threads per row
        {
            const int row = tid >> 1;
            const float* src = (ki < 32)
                ? (X     + (size_t)(m0 + row) * 1024 + (size_t)ki * KB)
                : (Hprev + (size_t)(m0 + row) * 1024 + (size_t)(ki - 32) * KB);
            const uint32_t rbase = base + (uint32_t)row * 128u;
            const uint32_t sk = ((uint32_t)(row & 7)) << 4;
            const int c0 = (tid & 1) * 4;
            #pragma unroll
            for (int c = 0; c < 4; c++)
                cp16(rbase + ((((uint32_t)(c0 + c)) << 4) ^ sk), src + (c0 + c) * 4);
        }
        // B: 256 rows (4 gates x 64 neurons) x 128B, 1 thread per row
        {
            const int g = tid >> 6, n = tid & 63;
            const float* w = (g == 0) ? Wf : (g == 1) ? Wi : (g == 2) ? Wc : Wo;
            const float* src = w + (size_t)(n0 + n) * 2048 + (size_t)ki * KB;
            const uint32_t rbase = base + A_BYTES + (uint32_t)tid * 128u;
            const uint32_t sk = ((uint32_t)(tid & 7)) << 4;
            #pragma unroll
            for (int c = 0; c < 8; c++)
                cp16(rbase + ((((uint32_t)c) << 4) ^ sk), src + c * 4);
        }
    };

    float acc[2][16][4];   // [m16 tile][gate*4 + n8 tile][frag]
    #pragma unroll
    for (int mt = 0; mt < 2; mt++)
        #pragma unroll
        for (int t = 0; t < 16; t++)
            #pragma unroll
            for (int c = 0; c < 4; c++) acc[mt][t][c] = 0.0f;

    // ---- prologue: stages 0,1 ----
    load_stage(0, 0); cp_commit();
    load_stage(1, 1); cp_commit();

    // ---- mainloop ----
    for (int i = 0; i < KITERS; i++) {
        const int li = i + STAGES - 1;
        if (li < KITERS) {
            int ls = li % STAGES;
            load_stage(ls, li);
        }
        cp_commit();            // commit every iter (possibly empty) to keep counts aligned
        cp_wait2();             // chunk i resident
        __syncthreads();

        const char* st = smem + (size_t)(i % STAGES) * STAGE_BYTES;
        const char* stB = st + A_BYTES;

        #pragma unroll
        for (int ks = 0; ks < 4; ks++) {
            const int k0 = ks * 8 + (lane & 3);
            uint32_t a[2][4];
            #pragma unroll
            for (int mt = 0; mt < 2; mt++) {
                const int r = wm * 32 + mt * 16 + (lane >> 2);
                a[mt][0] = f2tf(lds_elem(st, r,     k0));
                a[mt][1] = f2tf(lds_elem(st, r + 8, k0));
                a[mt][2] = f2tf(lds_elem(st, r,     k0 + 4));
                a[mt][3] = f2tf(lds_elem(st, r + 8, k0 + 4));
            }
            #pragma unroll
            for (int g = 0; g < 4; g++) {
                #pragma unroll
                for (int nt = 0; nt < 4; nt++) {
                    const int br = g * 64 + wn * 32 + nt * 8 + (lane >> 2);
                    const uint32_t b0 = f2tf(lds_elem(stB, br, k0));
                    const uint32_t b1 = f2tf(lds_elem(stB, br, k0 + 4));
                    mma_tf32(acc[0][g * 4 + nt], a[0], b0, b1);
                    mma_tf32(acc[1][g * 4 + nt], a[1], b0, b1);
                }
            }
        }
        __syncthreads();        // all warps done with slot before it is reloaded
    }

    // ---- fused epilogue: bias + activations + cell update ----
    #pragma unroll
    for (int mt = 0; mt < 2; mt++) {
        #pragma unroll
        for (int rr = 0; rr < 2; rr++) {
            const int m = m0 + wm * 32 + mt * 16 + (lane >> 2) + rr * 8;
            const float* crow = Cprev + (size_t)m * HDIM;
            float* oc = Out + (size_t)m * HDIM;
            float* oh = Out + (size_t)BATCHSZ * HDIM + (size_t)m * HDIM;
            #pragma unroll
            for (int nt = 0; nt < 4; nt++) {
                const int col = n0 + wn * 32 + nt * 8 + 2 * (lane & 3);
                const float2 bf = *(const float2*)(Bf + col);
                const float2 bi = *(const float2*)(Bi + col);
                const float2 bc = *(const float2*)(Bc + col);
                const float2 bo = *(const float2*)(Bo + col);
                const float2 cv = *(const float2*)(crow + col);
                float cn[2], hn[2];
                #pragma unroll
                for (int cc = 0; cc < 2; cc++) {
                    const int ci = rr * 2 + cc;
                    const float fv = acc[mt][0 * 4 + nt][ci] + (cc ? bf.y : bf.x);
                    const float iv = acc[mt][1 * 4 + nt][ci] + (cc ? bi.y : bi.x);
                    const float gv = acc[mt][2 * 4 + nt][ci] + (cc ? bc.y : bc.x);
                    const float ov = acc[mt][3 * 4 + nt][ci] + (cc ? bo.y : bo.x);
                    const float ft = sig_e(fv);
                    const float it = sig_e(iv);
                    const float gt = tanh_e(gv);
                    const float ot = sig_e(ov);
                    const float c2 = ft * (cc ? cv.y : cv.x) + it * gt;
                    cn[cc] = c2;
                    hn[cc] = ot * tanh_e(c2);
                }
                *(float2*)(oc + col) = make_float2(cn[0], cn[1]);
                *(float2*)(oh + col) = make_float2(hn[0], hn[1]);
            }
        }
    }
}

} // namespace

extern "C" void kernel_launch(void* const* d_in, const int* in_sizes, int n_in,
                              void* d_out, int out_size)
{
    const float* X  = (const float*)d_in[0];
    const float* C  = (const float*)d_in[1];
    const float* H  = (const float*)d_in[2];
    const float* Wf = (const float*)d_in[3];
    const float* Bf = (const float*)d_in[4];
    const float* Wi = (const float*)d_in[5];
    const float* Bi = (const float*)d_in[6];
    const float* Wc = (const float*)d_in[7];
    const float* Bc = (const float*)d_in[8];
    const float* Wo = (const float*)d_in[9];
    const float* Bo = (const float*)d_in[10];
    float* Out = (float*)d_out;

    cudaFuncSetAttribute(lstm_kernel, cudaFuncAttributeMaxDynamicSharedMemorySize, SMEM_TOTAL);
    dim3 grid(HDIM / BN, BATCHSZ / BM);   // (16, 128) = 2048 CTAs
    lstm_kernel<<<grid, 256, SMEM_TOTAL>>>(X, C, H, Wf, Bf, Wi, Bi, Wc, Bc, Wo, Bo, Out);
}

// round 4
// speedup vs baseline: 1.1121x; 1.1121x over previous
#include <cuda_runtime.h>
#include <cstdint>
#include <cstddef>

namespace {

constexpr int BM = 128;        // batch rows per CTA
constexpr int BN = 64;         // hidden cols per CTA (per gate; x4 gates)
constexpr int KB = 32;         // K elements per pipeline chunk
constexpr int STAGES = 4;
constexpr int KITERS = 2048 / KB;  // 64
constexpr int HDIM = 1024;
constexpr int BATCHSZ = 16384;

constexpr uint32_t A_BYTES = (uint32_t)BM * 128;        // 16 KB
constexpr uint32_t B_BYTES = (uint32_t)(4 * BN) * 128;  // 32 KB
constexpr uint32_t STAGE_BYTES = A_BYTES + B_BYTES;     // 48 KB
constexpr uint32_t SMEM_TOTAL = STAGES * STAGE_BYTES;   // 192 KB

// Pre-converted (tf32-RN) + pre-swizzled tile images.
// Apack: [m_block 128][ki 64][row 128][32 u32 swizzled]  = 128 MB
// Bpack: [n_block 16][ki 64][gate*64+n 256][32 u32 swizzled] = 32 MB
__device__ uint32_t Apack[(size_t)BATCHSZ * 2048];
__device__ uint32_t Bpack[(size_t)4 * HDIM * 2048];

__device__ __forceinline__ uint32_t smem_u32(const void* p) {
    uint32_t a;
    asm("{ .reg .u64 t; cvta.to.shared.u64 t, %1; cvt.u32.u64 %0, t; }" : "=r"(a) : "l"(p));
    return a;
}
__device__ __forceinline__ void cp16(uint32_t dst, const void* src) {
    asm volatile("cp.async.cg.shared.global [%0], [%1], 16;" :: "r"(dst), "l"(src));
}
__device__ __forceinline__ void cp_commit() { asm volatile("cp.async.commit_group;" ::: "memory"); }
__device__ __forceinline__ void cp_waitp()  { asm volatile("cp.async.wait_group 2;" ::: "memory"); }

__device__ __forceinline__ uint32_t f2tf(float x) {
    uint32_t r; asm("cvt.rna.tf32.f32 %0, %1;" : "=r"(r) : "f"(x)); return r;
}

__device__ __forceinline__ void ldsm4(uint32_t (&r)[4], uint32_t addr) {
    asm volatile("ldmatrix.sync.aligned.m8n8.x4.shared.b16 {%0,%1,%2,%3}, [%4];"
                 : "=r"(r[0]), "=r"(r[1]), "=r"(r[2]), "=r"(r[3]) : "r"(addr));
}

__device__ __forceinline__ void mma_tf32(float (&d)[4], const uint32_t (&a)[4],
                                         uint32_t b0, uint32_t b1) {
    asm volatile(
        "mma.sync.aligned.m16n8k8.row.col.f32.tf32.tf32.f32 "
        "{%0,%1,%2,%3}, {%4,%5,%6,%7}, {%8,%9}, {%0,%1,%2,%3};"
        : "+f"(d[0]), "+f"(d[1]), "+f"(d[2]), "+f"(d[3])
        : "r"(a[0]), "r"(a[1]), "r"(a[2]), "r"(a[3]), "r"(b0), "r"(b1));
}

__device__ __forceinline__ float sig_e(float x) {
    return __fdividef(1.0f, 1.0f + __expf(-x));
}
__device__ __forceinline__ float tanh_e(float x) {
    return __fdividef(2.0f, 1.0f + __expf(-2.0f * x)) - 1.0f;
}

// ---- pack kernels: fp32 -> tf32(RN), swizzled tile-image layout ----
__global__ void __launch_bounds__(256)
packA_kernel(const float* __restrict__ X, const float* __restrict__ H) {
    const uint32_t idx = blockIdx.x * 256 + threadIdx.x;  // one 16B chunk
    const uint32_t m  = idx >> 9;         // batch row
    const uint32_t cg = idx & 511;        // global k-chunk (k = cg*4)
    const float* src = (cg < 256) ? (X + (size_t)m * 1024 + cg * 4)
                                  : (H + (size_t)m * 1024 + (cg - 256) * 4);
    const float4 v = *(const float4*)src;
    uint4 o;
    o.x = f2tf(v.x); o.y = f2tf(v.y); o.z = f2tf(v.z); o.w = f2tf(v.w);
    const uint32_t mb = m >> 7, r = m & 127, ki = cg >> 3, c = cg & 7;
    const size_t dst = (((size_t)(mb * 64 + ki) * 128 + r) * 32) + ((c ^ (r & 7)) << 2);
    *(uint4*)(Apack + dst) = o;
}

__global__ void __launch_bounds__(256)
packB_kernel(const float* __restrict__ W, int gate) {
    const uint32_t idx = blockIdx.x * 256 + threadIdx.x;
    const uint32_t n  = idx >> 9;         // neuron
    const uint32_t cg = idx & 511;
    const float4 v = *(const float4*)(W + (size_t)n * 2048 + cg * 4);
    uint4 o;
    o.x = f2tf(v.x); o.y = f2tf(v.y); o.z = f2tf(v.z); o.w = f2tf(v.w);
    const uint32_t nb = n >> 6, nl = n & 63, ki = cg >> 3, c = cg & 7;
    const size_t dst = (((size_t)(nb * 64 + ki) * 256 + gate * 64 + nl) * 32) + ((c ^ (nl & 7)) << 2);
    *(uint4*)(Bpack + dst) = o;
}

// ---- main fused kernel ----
__global__ void __launch_bounds__(256, 1)
lstm_kernel(const float* __restrict__ Cprev,
            const float* __restrict__ Bf, const float* __restrict__ Bi,
            const float* __restrict__ Bc, const float* __restrict__ Bo,
            float* __restrict__ Out)
{
    extern __shared__ char smem[];
    const uint32_t sb = smem_u32(smem);
    const int tid  = threadIdx.x;
    const int wid  = tid >> 5;
    const int lane = tid & 31;
    const int wm   = wid & 3;     // 32-row M block of warp
    const int wn   = wid >> 2;    // 32-col N block of warp (within 64-col gate tile)
    const int bx = blockIdx.x;    // n block (16)
    const int by = blockIdx.y;    // m block (128)
    const int n0 = bx * BN;
    const int m0 = by * BM;

    auto load_stage = [&](int s, int ki) {
        const uint32_t base = sb + (uint32_t)s * STAGE_BYTES;
        const uint32_t* asrc = Apack + ((size_t)(by * 64 + ki) << 12);   // 4096 u32
        #pragma unroll
        for (int c = 0; c < 4; c++)
            cp16(base + (uint32_t)tid * 64 + c * 16, asrc + tid * 16 + c * 4);
        const uint32_t* bsrc = Bpack + ((size_t)(bx * 64 + ki) << 13);   // 8192 u32
        #pragma unroll
        for (int c = 0; c < 8; c++)
            cp16(base + A_BYTES + (uint32_t)tid * 128 + c * 16, bsrc + tid * 32 + c * 4);
    };

    float acc[2][16][4];
    #pragma unroll
    for (int mt = 0; mt < 2; mt++)
        #pragma unroll
        for (int t = 0; t < 16; t++)
            #pragma unroll
            for (int c = 0; c < 4; c++) acc[mt][t][c] = 0.0f;

    // per-lane ldmatrix address components
    const int lr = lane & 7, mi = lane >> 3;
    const uint32_t sw = (uint32_t)lr << 4;
    const uint32_t aRow = (uint32_t)(wm * 32 + (mi & 1) * 8 + lr);
    const uint32_t aChk = (uint32_t)(mi >> 1);
    const uint32_t bRow = (uint32_t)(wn * 32 + (mi >> 1) * 8 + lr);
    const uint32_t bChk = (uint32_t)(mi & 1);

    // ---- prologue ----
    load_stage(0, 0); cp_commit();
    load_stage(1, 1); cp_commit();
    load_stage(2, 2); cp_commit();

    // ---- mainloop: one __syncthreads per chunk ----
    for (int i = 0; i < KITERS; i++) {
        cp_waitp();               // stage i resident (<=2 groups pending)
        __syncthreads();          // also protects slot (i-1)%4 from overwrite

        const int li = i + STAGES - 1;
        if (li < KITERS) load_stage(li & (STAGES - 1), li);

        const uint32_t stA = sb + (uint32_t)(i & (STAGES - 1)) * STAGE_BYTES;
        const uint32_t stB = stA + A_BYTES;

        #pragma unroll
        for (int ks = 0; ks < 4; ks++) {
            uint32_t a[2][4];
            #pragma unroll
            for (int mt = 0; mt < 2; mt++)
                ldsm4(a[mt], stA + (aRow + mt * 16) * 128
                              + ((((uint32_t)(2 * ks) + aChk) << 4) ^ sw));
            #pragma unroll
            for (int g = 0; g < 4; g++) {
                #pragma unroll
                for (int p = 0; p < 2; p++) {
                    uint32_t b[4];
                    ldsm4(b, stB + (bRow + (uint32_t)(g * 64 + p * 16)) * 128
                              + ((((uint32_t)(2 * ks) + bChk) << 4) ^ sw));
                    mma_tf32(acc[0][g * 4 + 2 * p],     a[0], b[0], b[1]);
                    mma_tf32(acc[1][g * 4 + 2 * p],     a[1], b[0], b[1]);
                    mma_tf32(acc[0][g * 4 + 2 * p + 1], a[0], b[2], b[3]);
                    mma_tf32(acc[1][g * 4 + 2 * p + 1], a[1], b[2], b[3]);
                }
            }
        }
        cp_commit();
    }

    // ---- fused epilogue ----
    #pragma unroll
    for (int mt = 0; mt < 2; mt++) {
        #pragma unroll
        for (int rr = 0; rr < 2; rr++) {
            const int m = m0 + wm * 32 + mt * 16 + (lane >> 2) + rr * 8;
            const float* crow = Cprev + (size_t)m * HDIM;
            float* oc = Out + (size_t)m * HDIM;
            float* oh = Out + (size_t)BATCHSZ * HDIM + (size_t)m * HDIM;
            #pragma unroll
            for (int nt = 0; nt < 4; nt++) {
                const int col = n0 + wn * 32 + nt * 8 + 2 * (lane & 3);
                const float2 bf = *(const float2*)(Bf + col);
                const float2 bi = *(const float2*)(Bi + col);
                const float2 bc = *(const float2*)(Bc + col);
                const float2 bo = *(const float2*)(Bo + col);
                const float2 cv = *(const float2*)(crow + col);
                float cn[2], hn[2];
                #pragma unroll
                for (int cc = 0; cc < 2; cc++) {
                    const int ci = rr * 2 + cc;
                    const float fv = acc[mt][0 * 4 + nt][ci] + (cc ? bf.y : bf.x);
                    const float iv = acc[mt][1 * 4 + nt][ci] + (cc ? bi.y : bi.x);
                    const float gv = acc[mt][2 * 4 + nt][ci] + (cc ? bc.y : bc.x);
                    const float ov = acc[mt][3 * 4 + nt][ci] + (cc ? bo.y : bo.x);
                    const float ft = sig_e(fv);
                    const float it = sig_e(iv);
                    const float gt = tanh_e(gv);
                    const float ot = sig_e(ov);
                    const float c2 = ft * (cc ? cv.y : cv.x) + it * gt;
                    cn[cc] = c2;
                    hn[cc] = ot * tanh_e(c2);
                }
                *(float2*)(oc + col) = make_float2(cn[0], cn[1]);
                *(float2*)(oh + col) = make_float2(hn[0], hn[1]);
            }
        }
    }
}

} // namespace

extern "C" void kernel_launch(void* const* d_in, const int* in_sizes, int n_in,
                              void* d_out, int out_size)
{
    const float* X  = (const float*)d_in[0];
    const float* C  = (const float*)d_in[1];
    const float* H  = (const float*)d_in[2];
    const float* Wf = (const float*)d_in[3];
    const float* Bf = (const float*)d_in[4];
    const float* Wi = (const float*)d_in[5];
    const float* Bi = (const float*)d_in[6];
    const float* Wc = (const float*)d_in[7];
    const float* Bc = (const float*)d_in[8];
    const float* Wo = (const float*)d_in[9];
    const float* Bo = (const float*)d_in[10];
    float* Out = (float*)d_out;

    // pre-pack: tf32-convert + swizzle-image X|H and the four W matrices
    packA_kernel<<<(BATCHSZ * 512) / 256, 256>>>(X, H);
    packB_kernel<<<(HDIM * 512) / 256, 256>>>(Wf, 0);
    packB_kernel<<<(HDIM * 512) / 256, 256>>>(Wi, 1);
    packB_kernel<<<(HDIM * 512) / 256, 256>>>(Wc, 2);
    packB_kernel<<<(HDIM * 512) / 256, 256>>>(Wo, 3);

    cudaFuncSetAttribute(lstm_kernel, cudaFuncAttributeMaxDynamicSharedMemorySize, SMEM_TOTAL);
    dim3 grid(HDIM / BN, BATCHSZ / BM);   // (16, 128)
    lstm_kernel<<<grid, 256, SMEM_TOTAL>>>(C, Bf, Bi, Bc, Bo, Out);
}

// round 5
// speedup vs baseline: 1.4800x; 1.3308x over previous
#include <cuda_runtime.h>
#include <cstdint>
#include <cstddef>

namespace {

constexpr int BM = 128;        // batch rows per CTA
constexpr int BN = 64;         // hidden cols per CTA (per gate; x4 gates)
constexpr int KB = 32;         // K elements per pipeline chunk
constexpr int STAGES = 4;
constexpr int KITERS = 2048 / KB;  // 64
constexpr int HDIM = 1024;
constexpr int BATCHSZ = 16384;

constexpr uint32_t A_BYTES = (uint32_t)BM * 128;        // 16 KB
constexpr uint32_t B_BYTES = (uint32_t)(4 * BN) * 128;  // 32 KB
constexpr uint32_t STAGE_BYTES = A_BYTES + B_BYTES;     // 48 KB
constexpr uint32_t SMEM_TOTAL = STAGES * STAGE_BYTES;   // 192 KB

// Pre-converted (tf32-RN) + pre-swizzled tile images.
__device__ uint32_t Apack[(size_t)BATCHSZ * 2048];
__device__ uint32_t Bpack[(size_t)4 * HDIM * 2048];

__device__ __forceinline__ uint32_t smem_u32(const void* p) {
    uint32_t a;
    asm("{ .reg .u64 t; cvta.to.shared.u64 t, %1; cvt.u32.u64 %0, t; }" : "=r"(a) : "l"(p));
    return a;
}
__device__ __forceinline__ void cp16(uint32_t dst, const void* src) {
    asm volatile("cp.async.cg.shared.global [%0], [%1], 16;" :: "r"(dst), "l"(src));
}
__device__ __forceinline__ void cp_commit() { asm volatile("cp.async.commit_group;" ::: "memory"); }
__device__ __forceinline__ void cp_waitp()  { asm volatile("cp.async.wait_group 2;" ::: "memory"); }

__device__ __forceinline__ uint32_t f2tf(float x) {
    uint32_t r; asm("cvt.rna.tf32.f32 %0, %1;" : "=r"(r) : "f"(x)); return r;
}

__device__ __forceinline__ void ldsm4(uint32_t (&r)[4], uint32_t addr) {
    asm volatile("ldmatrix.sync.aligned.m8n8.x4.shared.b16 {%0,%1,%2,%3}, [%4];"
                 : "=r"(r[0]), "=r"(r[1]), "=r"(r[2]), "=r"(r[3]) : "r"(addr));
}

__device__ __forceinline__ void mma_tf32(float (&d)[4], const uint32_t (&a)[4],
                                         uint32_t b0, uint32_t b1) {
    asm volatile(
        "mma.sync.aligned.m16n8k8.row.col.f32.tf32.tf32.f32 "
        "{%0,%1,%2,%3}, {%4,%5,%6,%7}, {%8,%9}, {%0,%1,%2,%3};"
        : "+f"(d[0]), "+f"(d[1]), "+f"(d[2]), "+f"(d[3])
        : "r"(a[0]), "r"(a[1]), "r"(a[2]), "r"(a[3]), "r"(b0), "r"(b1));
}

__device__ __forceinline__ float sig_e(float x) {
    return __fdividef(1.0f, 1.0f + __expf(-x));
}
__device__ __forceinline__ float tanh_e(float x) {
    return __fdividef(2.0f, 1.0f + __expf(-2.0f * x)) - 1.0f;
}

// ---- pack kernels: fp32 -> tf32(RN), swizzled tile-image layout ----
__global__ void __launch_bounds__(256)
packA_kernel(const float* __restrict__ X, const float* __restrict__ H) {
    const uint32_t idx = blockIdx.x * 256 + threadIdx.x;  // one 16B chunk
    const uint32_t m  = idx >> 9;         // batch row
    const uint32_t cg = idx & 511;        // global k-chunk (k = cg*4)
    const float* src = (cg < 256) ? (X + (size_t)m * 1024 + cg * 4)
                                  : (H + (size_t)m * 1024 + (cg - 256) * 4);
    const float4 v = *(const float4*)src;
    uint4 o;
    o.x = f2tf(v.x); o.y = f2tf(v.y); o.z = f2tf(v.z); o.w = f2tf(v.w);
    const uint32_t mb = m >> 7, r = m & 127, ki = cg >> 3, c = cg & 7;
    const size_t dst = (((size_t)(mb * 64 + ki) * 128 + r) * 32) + ((c ^ (r & 7)) << 2);
    *(uint4*)(Apack + dst) = o;
}

__global__ void __launch_bounds__(256)
packB_kernel(const float* __restrict__ W, int gate) {
    const uint32_t idx = blockIdx.x * 256 + threadIdx.x;
    const uint32_t n  = idx >> 9;         // neuron
    const uint32_t cg = idx & 511;
    const float4 v = *(const float4*)(W + (size_t)n * 2048 + cg * 4);
    uint4 o;
    o.x = f2tf(v.x); o.y = f2tf(v.y); o.z = f2tf(v.z); o.w = f2tf(v.w);
    const uint32_t nb = n >> 6, nl = n & 63, ki = cg >> 3, c = cg & 7;
    const size_t dst = (((size_t)(nb * 64 + ki) * 256 + gate * 64 + nl) * 32) + ((c ^ (nl & 7)) << 2);
    *(uint4*)(Bpack + dst) = o;
}

// ---- main fused kernel: 512 threads, 16 warps as 4(M) x 4(N) ----
__global__ void __launch_bounds__(512, 1)
lstm_kernel(const float* __restrict__ Cprev,
            const float* __restrict__ Bf, const float* __restrict__ Bi,
            const float* __restrict__ Bc, const float* __restrict__ Bo,
            float* __restrict__ Out)
{
    extern __shared__ char smem[];
    const uint32_t sb = smem_u32(smem);
    const int tid  = threadIdx.x;
    const int wid  = tid >> 5;
    const int lane = tid & 31;
    const int wm   = wid & 3;     // 32-row M block of warp
    const int wn   = wid >> 2;    // 16-col N block of warp (within 64-col gate tile)
    const int bx = blockIdx.x;    // n block (16)
    const int by = blockIdx.y;    // m block (128)
    const int n0 = bx * BN;
    const int m0 = by * BM;

    // loader: 512 threads, A 16KB (32B/thread) + B 32KB (64B/thread)
    auto load_stage = [&](int s, int ki) {
        const uint32_t base = sb + (uint32_t)s * STAGE_BYTES;
        const uint32_t* asrc = Apack + ((size_t)(by * 64 + ki) << 12);   // 4096 u32
        #pragma unroll
        for (int c = 0; c < 2; c++)
            cp16(base + (uint32_t)tid * 32 + c * 16, asrc + tid * 8 + c * 4);
        const uint32_t* bsrc = Bpack + ((size_t)(bx * 64 + ki) << 13);   // 8192 u32
        #pragma unroll
        for (int c = 0; c < 4; c++)
            cp16(base + A_BYTES + (uint32_t)tid * 64 + c * 16, bsrc + tid * 16 + c * 4);
    };

    float acc[2][8][4];   // [m16 tile][gate*2 + n8 tile][frag]
    #pragma unroll
    for (int mt = 0; mt < 2; mt++)
        #pragma unroll
        for (int t = 0; t < 8; t++)
            #pragma unroll
            for (int c = 0; c < 4; c++) acc[mt][t][c] = 0.0f;

    // per-lane ldmatrix address components
    const int lr = lane & 7, mi = lane >> 3;
    const uint32_t sw = (uint32_t)lr << 4;
    const uint32_t aRow = (uint32_t)(wm * 32 + (mi & 1) * 8 + lr);
    const uint32_t aChk = (uint32_t)(mi >> 1);
    const uint32_t bRow = (uint32_t)(wn * 16 + (mi >> 1) * 8 + lr);
    const uint32_t bChk = (uint32_t)(mi & 1);

    // ---- prologue ----
    load_stage(0, 0); cp_commit();
    load_stage(1, 1); cp_commit();
    load_stage(2, 2); cp_commit();

    // ---- mainloop ----
    for (int i = 0; i < KITERS; i++) {
        cp_waitp();
        __syncthreads();

        const int li = i + STAGES - 1;
        if (li < KITERS) load_stage(li & (STAGES - 1), li);

        const uint32_t stA = sb + (uint32_t)(i & (STAGES - 1)) * STAGE_BYTES;
        const uint32_t stB = stA + A_BYTES;

        #pragma unroll
        for (int ks = 0; ks < 4; ks++) {
            uint32_t a[2][4];
            #pragma unroll
            for (int mt = 0; mt < 2; mt++)
                ldsm4(a[mt], stA + (aRow + mt * 16) * 128
                              + ((((uint32_t)(2 * ks) + aChk) << 4) ^ sw));
            #pragma unroll
            for (int g = 0; g < 4; g++) {
                uint32_t b[4];
                ldsm4(b, stB + (bRow + (uint32_t)(g * 64)) * 128
                          + ((((uint32_t)(2 * ks) + bChk) << 4) ^ sw));
                mma_tf32(acc[0][g * 2 + 0], a[0], b[0], b[1]);
                mma_tf32(acc[1][g * 2 + 0], a[1], b[0], b[1]);
                mma_tf32(acc[0][g * 2 + 1], a[0], b[2], b[3]);
                mma_tf32(acc[1][g * 2 + 1], a[1], b[2], b[3]);
            }
        }
        cp_commit();
    }

    // ---- fused epilogue (warp-local: all 4 gates in-register) ----
    #pragma unroll
    for (int mt = 0; mt < 2; mt++) {
        #pragma unroll
        for (int rr = 0; rr < 2; rr++) {
            const int m = m0 + wm * 32 + mt * 16 + (lane >> 2) + rr * 8;
            const float* crow = Cprev + (size_t)m * HDIM;
            float* oc = Out + (size_t)m * HDIM;
            float* oh = Out + (size_t)BATCHSZ * HDIM + (size_t)m * HDIM;
            #pragma unroll
            for (int nt = 0; nt < 2; nt++) {
                const int col = n0 + wn * 16 + nt * 8 + 2 * (lane & 3);
                const float2 bf = *(const float2*)(Bf + col);
                const float2 bi = *(const float2*)(Bi + col);
                const float2 bc = *(const float2*)(Bc + col);
                const float2 bo = *(const float2*)(Bo + col);
                const float2 cv = *(const float2*)(crow + col);
                float cn[2], hn[2];
                #pragma unroll
                for (int cc = 0; cc < 2; cc++) {
                    const int ci = rr * 2 + cc;
                    const float fv = acc[mt][0 * 2 + nt][ci] + (cc ? bf.y : bf.x);
                    const float iv = acc[mt][1 * 2 + nt][ci] + (cc ? bi.y : bi.x);
                    const float gv = acc[mt][2 * 2 + nt][ci] + (cc ? bc.y : bc.x);
                    const float ov = acc[mt][3 * 2 + nt][ci] + (cc ? bo.y : bo.x);
                    const float ft = sig_e(fv);
                    const float it = sig_e(iv);
                    const float gt = tanh_e(gv);
                    const float ot = sig_e(ov);
                    const float c2 = ft * (cc ? cv.y : cv.x) + it * gt;
                    cn[cc] = c2;
                    hn[cc] = ot * tanh_e(c2);
                }
                *(float2*)(oc + col) = make_float2(cn[0], cn[1]);
                *(float2*)(oh + col) = make_float2(hn[0], hn[1]);
            }
        }
    }
}

} // namespace

extern "C" void kernel_launch(void* const* d_in, const int* in_sizes, int n_in,
                              void* d_out, int out_size)
{
    const float* X  = (const float*)d_in[0];
    const float* C  = (const float*)d_in[1];
    const float* H  = (const float*)d_in[2];
    const float* Wf = (const float*)d_in[3];
    const float* Bf = (const float*)d_in[4];
    const float* Wi = (const float*)d_in[5];
    const float* Bi = (const float*)d_in[6];
    const float* Wc = (const float*)d_in[7];
    const float* Bc = (const float*)d_in[8];
    const float* Wo = (const float*)d_in[9];
    const float* Bo = (const float*)d_in[10];
    float* Out = (float*)d_out;

    packA_kernel<<<(BATCHSZ * 512) / 256, 256>>>(X, H);
    packB_kernel<<<(HDIM * 512) / 256, 256>>>(Wf, 0);
    packB_kernel<<<(HDIM * 512) / 256, 256>>>(Wi, 1);
    packB_kernel<<<(HDIM * 512) / 256, 256>>>(Wc, 2);
    packB_kernel<<<(HDIM * 512) / 256, 256>>>(Wo, 3);

    cudaFuncSetAttribute(lstm_kernel, cudaFuncAttributeMaxDynamicSharedMemorySize, SMEM_TOTAL);
    dim3 grid(HDIM / BN, BATCHSZ / BM);   // (16, 128)
    lstm_kernel<<<grid, 512, SMEM_TOTAL>>>(C, Bf, Bi, Bc, Bo, Out);
}